// round 17
// baseline (speedup 1.0000x reference)
#include <cuda_runtime.h>
#include <cuda_fp16.h>
#include <cstdint>

// ---------------------------------------------------------------------------
// DCNv2 + GroupNorm16.  B=4, Cin=Cout=256, H=W=64, K=3, s=1, p=1, g=16.
// Fused tensor-core kernel (M=128 tiles, grid 128), now 1024 thr / 32 warps
// (warp tile 32x32) for 2x occupancy. K-chunks of 64.
//  phase1 = offset conv HMMA (fp16 im2col A; MMA on warps 0-15) + meta;
//  phase2 = deformable-sampled HMMA GEMM, fp16 gathers + fp16 bilinear
//  combine (zero converts), B single fp16. One barrier per chunk.
//  GN partial stats fused. compute_103 baseline PTX only.
// ---------------------------------------------------------------------------

// ---- device-global scratch -------------------------------------------------
__device__ __half g_xH[4 * 4096 * 256];       // x NHWC fp16
__device__ __half g_wF16[72 * 256 * 32];      // main weight fp16 [ci32][o][k]
__device__ __half g_wOf[72 * 32 * 32];        // offset weight fp16 [ci32][o32][k]
__device__ float  g_conv[4 * 256 * 4096];     // conv out (pre-GN)
__device__ float  g_psum[64 * 32];            // per-(bg,tile) partial sums
__device__ float  g_pssum[64 * 32];
__device__ float  g_mu[64];
__device__ float  g_rs[64];

// ---- PTX helpers ----------------------------------------------------------
__device__ __forceinline__ unsigned smem_u32(const void* p) {
    unsigned a;
    asm("{ .reg .u64 t; cvta.to.shared.u64 t, %1; cvt.u32.u64 %0, t; }"
        : "=r"(a) : "l"(p));
    return a;
}
#define CP16(s, g) asm volatile("cp.async.cg.shared.global [%0], [%1], 16;" :: "r"(s), "l"(g) : "memory")
#define CP_COMMIT() asm volatile("cp.async.commit_group;" ::: "memory")
#define CP_WAIT0()  asm volatile("cp.async.wait_group 0;" ::: "memory")

#define LDSM4(r, addr)                                                        \
    asm volatile("ldmatrix.sync.aligned.m8n8.x4.shared.b16 {%0,%1,%2,%3}, [%4];" \
                 : "=r"((r)[0]), "=r"((r)[1]), "=r"((r)[2]), "=r"((r)[3])     \
                 : "r"(addr))

#define MMA(ap, a, b0, b1)                                                    \
    asm volatile("mma.sync.aligned.m16n8k16.row.col.f32.f16.f16.f32 "         \
                 "{%0,%1,%2,%3}, {%4,%5,%6,%7}, {%8,%9}, {%0,%1,%2,%3};"      \
                 : "+f"((ap)[0]), "+f"((ap)[1]), "+f"((ap)[2]), "+f"((ap)[3]) \
                 : "r"((a)[0]), "r"((a)[1]), "r"((a)[2]), "r"((a)[3]),        \
                   "r"(b0), "r"(b1))

#define U2H(u) (*reinterpret_cast<const __half2*>(&(u)))
#define H2U(h) (*reinterpret_cast<const unsigned*>(&(h)))

// ---------------------------------------------------------------------------
// x NCHW fp32 -> NHWC fp16
// ---------------------------------------------------------------------------
__global__ void k_xT(const float* __restrict__ x) {
    __shared__ float t[32][33];
    int bx = blockIdx.x;                    // 4096 = b(4) * cblk(8) * pxblk(128)
    int pxb = bx & 127, cb = (bx >> 7) & 7, b = bx >> 10;
    int tx = threadIdx.x & 31, ty = threadIdx.x >> 5;
#pragma unroll
    for (int i = 0; i < 4; i++) {
        int c = cb * 32 + ty + i * 8;
        t[ty + i * 8][tx] = x[(((size_t)(b * 256 + c)) << 12) + pxb * 32 + tx];
    }
    __syncthreads();
#pragma unroll
    for (int i = 0; i < 4; i++) {
        int px = pxb * 32 + ty + i * 8;
        g_xH[(((size_t)b << 12) + px) * 256 + cb * 32 + tx] =
            __float2half(t[tx][ty + i * 8]);
    }
}

// ---------------------------------------------------------------------------
// main weight [O][C][3][3] -> fp16 [ci32][o][k32]; ci32 = tap*8+cb, c=cb*32+k
// ---------------------------------------------------------------------------
__global__ void k_prepW(const float* __restrict__ w) {
    int o = blockIdx.x;
    for (int idx = threadIdx.x; idx < 2304; idx += 256) {
        int ci = idx >> 5, k = idx & 31;
        int tap = ci >> 3, c = ((ci & 7) << 5) + k;
        g_wF16[(size_t)ci * 8192 + o * 32 + k] =
            __float2half(w[o * 2304 + c * 9 + tap]);
    }
}

// ---------------------------------------------------------------------------
// offset weight [27][C][3][3] -> fp16 [ci32][o(32, >=27 zero)][k32]
// ---------------------------------------------------------------------------
__global__ void k_offW(const float* __restrict__ wof) {
    int ci = blockIdx.x;
    int tap = ci >> 3, cb = ci & 7;
    for (int i = threadIdx.x; i < 1024; i += 256) {
        int o = i >> 5, k = i & 31;
        int c = (cb << 5) + k;
        float v = (o < 27) ? wof[o * 2304 + c * 9 + tap] : 0.f;
        g_wOf[ci * 1024 + i] = __float2half(v);
    }
}

// ---------------------------------------------------------------------------
// Fused kernel. Grid 128 = (b, 32 px-tiles of 128). 1024 threads, 32 warps.
// SMEM (dynamic, 147456 B), rows padded to 144B:
//   SA[buf]: 128 rows x 144B = 18432 each -> [0, 36864)
//   SB[buf]: 256 rows x 144B = 36864 each -> [36864, 110592)
//     (phase1 uses first 32 rows of each SB buf; om scratch overlays SB(0))
//   META_I: idx[9][128][4] int        -> [110592, 129024)
//   META_W: wgt[9][128][4] fp16x2-dup -> [129024, 147456)
// ---------------------------------------------------------------------------
#define SA(buf)   ((buf) * 18432)
#define SB(buf)   (36864 + (buf) * 36864)
#define META_I    110592
#define META_W    129024
#define SMEM_TOTAL 147456

__global__ __launch_bounds__(1024, 1) void k_mainTC(const float* __restrict__ bof,
                                                    const float* __restrict__ bias) {
    extern __shared__ char sm[];
    unsigned smb = smem_u32(sm);
    int tid = threadIdx.x, lane = tid & 31, wid = tid >> 5;
    int b = blockIdx.x >> 5;
    int tile = blockIdx.x & 31;
    int p0 = tile << 7;

    int px = tid >> 3, seg = tid & 7;     // A staging role: 8 ch per thread
    unsigned aoff = (unsigned)((lane & 15) * 144 + (lane >> 4) * 16);
    unsigned boff = (unsigned)((lane & 7) * 144 + ((lane >> 3) & 1) * 16 +
                               (lane >> 4) * 1152);
    unsigned ao = (unsigned)(px * 144 + seg * 16);
    const __half* xh = g_xH + ((size_t)b << 20);

    // =======================================================================
    // Phase 1: offset conv HMMA. A staged by all 32 warps; MMA on warps 0-15
    // (wm1 0..7 x wn1 0..1, warp tile 16x16, 4 ksteps). 36 chunks of 64.
    // =======================================================================
    {
        int wm1 = wid & 7, wn1 = (wid >> 3) & 1;
        bool mmaw = wid < 16;
        float acc1[2][4];
#pragma unroll
        for (int i = 0; i < 2; i++)
#pragma unroll
            for (int j = 0; j < 4; j++) acc1[i][j] = 0.f;

        int gp = p0 + px, h = gp >> 6, w = gp & 63;
        uint4 qA;
        auto loadA1 = [&](int ci) {
            int tap = ci >> 2, cb = ci & 3;
            int py = h + tap / 3 - 1, pxx = w + tap % 3 - 1;
            if (py >= 0 && py < 64 && pxx >= 0 && pxx < 64) {
                qA = *(const uint4*)(xh + (((size_t)(py * 64 + pxx)) << 8) +
                                     (cb << 6) + (seg << 3));
            } else {
                qA = make_uint4(0u, 0u, 0u, 0u);
            }
        };
        auto loadB1 = [&](int ci, int buf) {
            if (tid < 256) {
                int tap = ci >> 2, cb = ci & 3;
                int row = tid >> 3, q = tid & 7;
                const __half* src = g_wOf +
                    (size_t)(tap * 8 + cb * 2 + (q >> 2)) * 1024 + row * 32 +
                    (q & 3) * 8;
                CP16(smb + SB(buf) + row * 144 + q * 16, src);
            }
            CP_COMMIT();
        };

        loadA1(0);
        loadB1(0, 0);
#pragma unroll 1
        for (int ci = 0; ci < 36; ci++) {
            int buf = ci & 1;
            *(uint4*)(sm + SA(buf) + ao) = qA;
            CP_WAIT0();
            __syncthreads();
            if (ci < 35) { loadA1(ci + 1); loadB1(ci + 1, buf ^ 1); }
            if (mmaw) {
                unsigned aB = smb + (unsigned)(SA(buf) + wm1 * 2304) + aoff;
                unsigned bB = smb + (unsigned)(SB(buf) + wn1 * 2304) + boff;
#pragma unroll
                for (int ks = 0; ks < 4; ks++) {
                    unsigned ah[4], bh[4];
                    LDSM4(ah, aB + ks * 32);
                    LDSM4(bh, bB + ks * 32);
                    MMA(acc1[0], ah, bh[0], bh[1]);
                    MMA(acc1[1], ah, bh[2], bh[3]);
                }
            }
        }
        __syncthreads();
        // om scratch (128 x 32 f32) overlaying SB(0)
        float* som = (float*)(sm + SB(0));
        if (mmaw) {
            int row = wm1 * 16 + (lane >> 2);
            int col = wn1 * 16 + (lane & 3) * 2;
#pragma unroll
            for (int nt = 0; nt < 2; nt++) {
                int c = col + nt * 8;
                som[row * 32 + c] = acc1[nt][0];
                som[row * 32 + c + 1] = acc1[nt][1];
                som[(row + 8) * 32 + c] = acc1[nt][2];
                som[(row + 8) * 32 + c + 1] = acc1[nt][3];
            }
        }
        __syncthreads();
        // bilinear meta -> smem META (idx int, weight*mask as fp16x2-dup)
        int* sIdx = (int*)(sm + META_I);
        unsigned* sWgtH = (unsigned*)(sm + META_W);
        for (int idx = tid; idx < 1152; idx += 1024) {
            int pr = idx / 9, k = idx - pr * 9;
            float ay = som[pr * 32 + k] + __ldg(bof + k);
            float ax = som[pr * 32 + k + 9] + __ldg(bof + k + 9);
            float am = som[pr * 32 + k + 18] + __ldg(bof + k + 18);
            float m = 1.f / (1.f + __expf(-am));
            int gp2 = p0 + pr, hh = gp2 >> 6, ww = gp2 & 63;
            float py = (float)(hh + k / 3 - 1) + ay;
            float pxx = (float)(ww + (k - (k / 3) * 3) - 1) + ax;
            float y0f = floorf(py), x0f = floorf(pxx);
            float wy1 = py - y0f, wx1 = pxx - x0f;
            int y0 = (int)y0f, x0 = (int)x0f;
            int mo = (k * 128 + pr) * 4;
#pragma unroll
            for (int j = 0; j < 4; j++) {
                int dy = j >> 1, dx = j & 1;
                int yy = y0 + dy, xx = x0 + dx;
                float wv = (dy ? wy1 : 1.f - wy1) * (dx ? wx1 : 1.f - wx1);
                bool valid = (yy >= 0) && (yy < 64) && (xx >= 0) && (xx < 64);
                int yc = min(max(yy, 0), 63), xc = min(max(xx, 0), 63);
                sIdx[mo + j] = yc * 64 + xc;
                float wvm = valid ? wv * m : 0.f;
                unsigned hv = (unsigned)__half_as_ushort(__float2half(wvm));
                sWgtH[mo + j] = hv | (hv << 16);
            }
        }
        __syncthreads();
    }

    // =======================================================================
    // Phase 2: main deformable GEMM, 36 chunks of 64.
    // 32 warps = (wm 0..3) x (wn 0..7), warp tile 32x32, 4 ksteps.
    // fp16 gathers (1 uint4/corner/thread) + fp16 bilinear combine.
    // =======================================================================
    int wm = wid & 3, wn = wid >> 2;
    float acc[32];
#pragma unroll
    for (int i = 0; i < 32; i++) acc[i] = 0.f;

    int4 mi;
    uint4 mwh;                 // 4 fp16x2-dup corner weights
    __half2 sH[4];             // sampled 8 channels (fp16x2)
    uint4 r0, r1;              // two raw corners (8 fp16 each)
    const int* sIdx = (const int*)(sm + META_I);
    const unsigned* sWgtH = (const unsigned*)(sm + META_W);

    auto meta2 = [&](int tap) {
        mi = *(const int4*)(sIdx + (tap * 128 + px) * 4);
        mwh = *(const uint4*)(sWgtH + (tap * 128 + px) * 4);
    };
    auto loadB2 = [&](int ci, int buf) {
        int tap = ci >> 2, cb = ci & 3;
        int row = tid & 255, sg = tid >> 8;   // 4 segments x 32B
        const __half* g = g_wF16 +
            (size_t)(tap * 8 + cb * 2 + (sg >> 1)) * 8192 + row * 32 +
            (sg & 1) * 16;
        unsigned s = smb + SB(buf) + row * 144 + sg * 32;
        CP16(s, g); CP16(s + 16, g + 8);
        CP_COMMIT();
    };
    auto issue01 = [&](int cb) {
        unsigned cbase = ((unsigned)cb << 6) + ((unsigned)seg << 3);
        r0 = *(const uint4*)(xh + (((size_t)mi.x) << 8) + cbase);
        r1 = *(const uint4*)(xh + (((size_t)mi.y) << 8) + cbase);
    };
    auto consume01 = [&]() {
        __half2 w0 = U2H(mwh.x), w1 = U2H(mwh.y);
        sH[0] = __hfma2(w1, U2H(r1.x), __hmul2(w0, U2H(r0.x)));
        sH[1] = __hfma2(w1, U2H(r1.y), __hmul2(w0, U2H(r0.y)));
        sH[2] = __hfma2(w1, U2H(r1.z), __hmul2(w0, U2H(r0.z)));
        sH[3] = __hfma2(w1, U2H(r1.w), __hmul2(w0, U2H(r0.w)));
    };
    auto issue23 = [&](int cb) {
        unsigned cbase = ((unsigned)cb << 6) + ((unsigned)seg << 3);
        r0 = *(const uint4*)(xh + (((size_t)mi.z) << 8) + cbase);
        r1 = *(const uint4*)(xh + (((size_t)mi.w) << 8) + cbase);
    };
    auto consume23 = [&]() {
        __half2 w2 = U2H(mwh.z), w3 = U2H(mwh.w);
        sH[0] = __hfma2(w3, U2H(r1.x), __hfma2(w2, U2H(r0.x), sH[0]));
        sH[1] = __hfma2(w3, U2H(r1.y), __hfma2(w2, U2H(r0.y), sH[1]));
        sH[2] = __hfma2(w3, U2H(r1.z), __hfma2(w2, U2H(r0.z), sH[2]));
        sH[3] = __hfma2(w3, U2H(r1.w), __hfma2(w2, U2H(r0.w), sH[3]));
    };
    auto kstep = [&](unsigned ab, unsigned bb, int ks) {
        unsigned ah0[4], ah1[4];
        LDSM4(ah0, ab + ks * 32);
        LDSM4(ah1, ab + ks * 32 + 2304);
#pragma unroll
        for (int ntp = 0; ntp < 2; ntp++) {
            unsigned bh[4];
            LDSM4(bh, bb + ntp * 2304 + ks * 32);
            MMA(&acc[(ntp * 2) * 4], ah0, bh[0], bh[1]);
            MMA(&acc[(ntp * 2 + 1) * 4], ah0, bh[2], bh[3]);
            MMA(&acc[(4 + ntp * 2) * 4], ah1, bh[0], bh[1]);
            MMA(&acc[(4 + ntp * 2 + 1) * 4], ah1, bh[2], bh[3]);
        }
    };

    // prologue: compute sH for chunk 0 (eager), issue B chunk 0
    meta2(0);
    issue01(0); consume01();
    issue23(0); consume23();
    loadB2(0, 0);

#pragma unroll 1
    for (int ci = 0; ci < 36; ci++) {
        int buf = ci & 1;
        *(uint4*)(sm + SA(buf) + ao) =
            make_uint4(H2U(sH[0]), H2U(sH[1]), H2U(sH[2]), H2U(sH[3]));
        CP_WAIT0();
        __syncthreads();

        int cn = ci + 1;
        bool more = cn < 36;
        int cb2 = cn & 3;
        if (more) {
            if (cb2 == 0) meta2(cn >> 2);
            issue01(cb2);
            loadB2(cn, buf ^ 1);
        }
        unsigned ab = smb + (unsigned)(SA(buf) + wm * 4608) + aoff;
        unsigned bb = smb + (unsigned)(SB(buf) + wn * 4608) + boff;
        kstep(ab, bb, 0);
        kstep(ab, bb, 1);
        if (more) { consume01(); issue23(cb2); }
        kstep(ab, bb, 2);
        kstep(ab, bb, 3);
        if (more) consume23();
        // no end-of-loop barrier (next iter's mid barrier orders reuse)
    }
    __syncthreads();

    // ---- epilogue: bias add, store, fused GN partial stats ----
    float pg[2] = {0.f, 0.f};
    float pq[2] = {0.f, 0.f};
    int pxb = p0 + wm * 32 + (lane >> 2);
#pragma unroll
    for (int mt = 0; mt < 2; mt++) {
#pragma unroll
        for (int nt = 0; nt < 4; nt++) {
            float* ap = &acc[(mt * 4 + nt) * 4];
            int o = wn * 32 + nt * 8 + (lane & 3) * 2;
            float bv0 = __ldg(bias + o), bv1 = __ldg(bias + o + 1);
            int pxm = pxb + mt * 16;
            size_t ra = (((size_t)(b * 256 + o)) << 12) + pxm;
            size_t rb = ra + 4096;
            float v0 = ap[0] + bv0, v1 = ap[1] + bv1;
            float v2 = ap[2] + bv0, v3 = ap[3] + bv1;
            g_conv[ra] = v0;
            g_conv[rb] = v1;
            g_conv[ra + 8] = v2;
            g_conv[rb + 8] = v3;
            int j = nt >> 1;
            pg[j] += v0 + v1 + v2 + v3;
            pq[j] += v0 * v0 + v1 * v1 + v2 * v2 + v3 * v3;
        }
    }
#pragma unroll
    for (int j = 0; j < 2; j++) {
#pragma unroll
        for (int s = 16; s > 0; s >>= 1) {
            pg[j] += __shfl_down_sync(0xFFFFFFFFu, pg[j], s);
            pq[j] += __shfl_down_sync(0xFFFFFFFFu, pq[j], s);
        }
    }
    float* red = (float*)sm;   // 32 warps x 4 floats
    if (lane == 0) {
        red[wid * 4 + 0] = pg[0];
        red[wid * 4 + 1] = pg[1];
        red[wid * 4 + 2] = pq[0];
        red[wid * 4 + 3] = pq[1];
    }
    __syncthreads();
    if (tid < 32) {
        int g = tid >> 1, which = tid & 1;   // 16 groups x {sum,ssum}
        int wnb = g >> 1, jj = g & 1;
        float v = 0.f;
#pragma unroll
        for (int wmi = 0; wmi < 4; wmi++)
            v += red[(wnb * 4 + wmi) * 4 + jj + 2 * which];
        if (which == 0) g_psum[(b * 16 + g) * 32 + tile] = v;
        else            g_pssum[(b * 16 + g) * 32 + tile] = v;
    }
}

// ---------------------------------------------------------------------------
// GN stats finalize: 64 blocks x 32 threads
// ---------------------------------------------------------------------------
__global__ void k_statsF() {
    int bg = blockIdx.x, t = threadIdx.x;
    float s = g_psum[bg * 32 + t];
    float q = g_pssum[bg * 32 + t];
#pragma unroll
    for (int o = 16; o > 0; o >>= 1) {
        s += __shfl_down_sync(0xFFFFFFFFu, s, o);
        q += __shfl_down_sync(0xFFFFFFFFu, q, o);
    }
    if (t == 0) {
        float mu = s * (1.f / 65536.f);
        float var = q * (1.f / 65536.f) - mu * mu;
        g_mu[bg] = mu;
        g_rs[bg] = rsqrtf(var + 1e-5f);
    }
}

// ---------------------------------------------------------------------------
// Normalize + affine -> d_out.  2048 blocks x 256 thr x 2 float4.
// ---------------------------------------------------------------------------
__global__ void k_norm(const float* __restrict__ gamma,
                       const float* __restrict__ beta,
                       float* __restrict__ out) {
    int i = blockIdx.x * 512 + threadIdx.x;
#pragma unroll
    for (int t = 0; t < 2; t++, i += 256) {
        float4 v = ((const float4*)g_conv)[i];
        int bc = i >> 10;
        int c = bc & 255, b = bc >> 8;
        int bg = b * 16 + (c >> 4);
        float sc = g_rs[bg] * gamma[c];
        float sh = beta[c] - g_mu[bg] * sc;
        v.x = v.x * sc + sh;
        v.y = v.y * sc + sh;
        v.z = v.z * sc + sh;
        v.w = v.w * sc + sh;
        ((float4*)out)[i] = v;
    }
}

// ---------------------------------------------------------------------------
extern "C" void kernel_launch(void* const* d_in, const int* in_sizes, int n_in,
                              void* d_out, int out_size) {
    const float* x = nullptr;
    const float* w_off = nullptr;
    const float* b_off = nullptr;
    const float* weight = nullptr;
    const float* v256[3] = {nullptr, nullptr, nullptr};
    int n256 = 0;
    for (int i = 0; i < n_in; i++) {
        int s = in_sizes[i];
        const float* ptr = (const float*)d_in[i];
        if (s == 4194304) x = ptr;
        else if (s == 62208) w_off = ptr;
        else if (s == 27) b_off = ptr;
        else if (s == 589824) weight = ptr;
        else if (s == 256 && n256 < 3) v256[n256++] = ptr;
    }
    const float* bias  = v256[0];
    const float* gamma = v256[1];
    const float* beta  = v256[2];
    float* out = (float*)d_out;

    cudaFuncSetAttribute(k_mainTC, cudaFuncAttributeMaxDynamicSharedMemorySize,
                         SMEM_TOTAL);

    k_xT<<<4096, 256>>>(x);
    k_prepW<<<256, 256>>>(weight);
    k_offW<<<72, 256>>>(w_off);
    k_mainTC<<<128, 1024, SMEM_TOTAL>>>(b_off, bias);
    k_statsF<<<64, 32>>>();
    k_norm<<<2048, 256>>>(gamma, beta, out);
}